// round 8
// baseline (speedup 1.0000x reference)
#include <cuda_runtime.h>
#include <cuda_bf16.h>
#include <cstdint>
#include <math.h>

// Problem dims
#define BB  128
#define TT  31
#define TP1 32
#define EE  512
#define HH  512
#define H4  2048
#define VV  10000
#define AA  2048
#define MTOT 4096   // (T+1)*B rows
#define NCTA 128    // persistent grid size

// ---------------- device scratch (static, no allocs) ----------------
__device__ float g_c    [BB*HH];
__device__ float g_attnx[MTOT*AA];
__device__ float g_attdx[MTOT*EE];
__device__ float g_alogp[8*BB*AA];     // attn-logit split-K partials (z=8)
__device__ float g_x2p  [32*BB*EE];    // x2 partials (z=32)
__device__ float g_gp   [8*BB*H4];     // gate partials (z=8)
__device__ int      g_bar_count;
__device__ unsigned g_bar_gen;

// bf16 split activation buffers
__device__ __nv_bfloat16 g_xs_hi [MTOT*EE], g_xs_lo [MTOT*EE];
__device__ __nv_bfloat16 g_hid_hi[MTOT*HH], g_hid_lo[MTOT*HH];
__device__ __nv_bfloat16 g_xh_hi [BB*1024], g_xh_lo [BB*1024];   // [x2|h]
__device__ __nv_bfloat16 g_att_hi[BB*AA],   g_att_lo[BB*AA];

// bf16 split weights
__device__ __nv_bfloat16 g_Woh[VV*HH],   g_Wol[VV*HH];     // W_out
__device__ __nv_bfloat16 g_Wnh[AA*EE],   g_Wnl[AA*EE];     // W_attn x-part
__device__ __nv_bfloat16 g_Wn2h[AA*HH],  g_Wn2l[AA*HH];    // W_attn h-part
__device__ __nv_bfloat16 g_Wdh[EE*EE],   g_Wdl[EE*EE];     // W_attd x-part
__device__ __nv_bfloat16 g_Wd2h[EE*AA],  g_Wd2l[EE*AA];    // W_attd a-part
__device__ __nv_bfloat16 g_Wch[H4*1024], g_Wcl[H4*1024];   // [W_ih|W_hh]

// ================= warp-MMA helpers (sm_80+ baseline PTX only) =================
__device__ __forceinline__ uint32_t smem_u32(const void* p) {
    uint32_t a;
    asm("{ .reg .u64 t; cvta.to.shared.u64 t, %1; cvt.u32.u64 %0, t; }" : "=r"(a) : "l"(p));
    return a;
}
__device__ __forceinline__ uint32_t sw128(uint32_t b) { return b ^ ((b >> 3) & 0x70); }

__device__ __forceinline__ void ldsm_x4(uint32_t* r, uint32_t addr) {
    asm volatile("ldmatrix.sync.aligned.m8n8.x4.shared.b16 {%0,%1,%2,%3}, [%4];"
                 : "=r"(r[0]), "=r"(r[1]), "=r"(r[2]), "=r"(r[3]) : "r"(addr));
}
__device__ __forceinline__ void ldsm_x2(uint32_t* r, uint32_t addr) {
    asm volatile("ldmatrix.sync.aligned.m8n8.x2.shared.b16 {%0,%1}, [%2];"
                 : "=r"(r[0]), "=r"(r[1]) : "r"(addr));
}
__device__ __forceinline__ void mma16816(float* d, const uint32_t* a, const uint32_t* b) {
    asm volatile("mma.sync.aligned.m16n8k16.row.col.f32.bf16.bf16.f32 "
                 "{%0,%1,%2,%3}, {%4,%5,%6,%7}, {%8,%9}, {%0,%1,%2,%3};"
                 : "+f"(d[0]), "+f"(d[1]), "+f"(d[2]), "+f"(d[3])
                 : "r"(a[0]), "r"(a[1]), "r"(a[2]), "r"(a[3]), "r"(b[0]), "r"(b[1]));
}

__device__ __forceinline__ void split_write(float x, __nv_bfloat16* hi, __nv_bfloat16* lo, size_t i) {
    __nv_bfloat16 h = __float2bfloat16(x);
    hi[i] = h;
    lo[i] = __float2bfloat16(x - __bfloat162float(h));
}

__device__ __forceinline__ float sigmoidf_(float x) {
    return 1.0f / (1.0f + expf(-x));
}

// ============ big warp-MMA split-bf16 GEMM: C = A@B^T (+bias) ============
// A: [M x K] hi/lo, M mult of 128; B: [Ntot x K] hi/lo (row-guarded); K mult of 64.
__global__ void __launch_bounds__(256, 2)
gemm_mma_kernel(const __nv_bfloat16* __restrict__ Ahi,
                const __nv_bfloat16* __restrict__ Alo,
                const __nv_bfloat16* __restrict__ Bhi,
                const __nv_bfloat16* __restrict__ Blo,
                const float* __restrict__ bias,
                float* __restrict__ C, int ldc, int Ntot, int K)
{
    extern __shared__ char smem[];
    const uint32_t sb = smem_u32(smem);
    const int tid = threadIdx.x;
    const int wid = tid >> 5;
    const int lane = tid & 31;
    const int warp_m = wid & 1;
    const int warp_n = wid >> 1;
    const int bm = blockIdx.y * 128;
    const int bn = blockIdx.x * 128;

    float acc[4][4][4];
    #pragma unroll
    for (int i = 0; i < 4; i++)
        #pragma unroll
        for (int j = 0; j < 4; j++)
            #pragma unroll
            for (int r = 0; r < 4; r++) acc[i][j][r] = 0.0f;

    const __nv_bfloat16* srcs[4] = {Ahi, Alo, Bhi, Blo};

    const int nchunks = K >> 6;
    for (int kc = 0; kc < nchunks; kc++) {
        if (kc > 0) __syncthreads();
        #pragma unroll
        for (int t = 0; t < 4; t++) {
            const __nv_bfloat16* src = srcs[t];
            const uint32_t dstbase = t * 16384;
            #pragma unroll
            for (int j = 0; j < 4; j++) {
                int v = tid + j * 256;
                int row = v >> 3, c8 = v & 7;
                uint4 val = make_uint4(0, 0, 0, 0);
                if (t < 2) {
                    val = *(const uint4*)(src + (size_t)(bm + row) * K + kc * 64 + c8 * 8);
                } else {
                    int gn = bn + row;
                    if (gn < Ntot)
                        val = *(const uint4*)(src + (size_t)gn * K + kc * 64 + c8 * 8);
                }
                *(uint4*)(smem + dstbase + sw128(row * 128 + c8 * 16)) = val;
            }
        }
        __syncthreads();

        #pragma unroll
        for (int pass = 0; pass < 3; pass++) {
            const uint32_t abase = sb + ((pass == 2) ? 16384 : 0);
            const uint32_t bbase = sb + 32768 + ((pass == 1) ? 16384 : 0);
            #pragma unroll
            for (int kk = 0; kk < 4; kk++) {
                uint32_t afr[4][4];
                #pragma unroll
                for (int mt = 0; mt < 4; mt++) {
                    int row = warp_m * 64 + mt * 16 + (lane & 15);
                    int kb  = kk * 32 + ((lane >> 4) << 4);
                    ldsm_x4(afr[mt], abase + sw128(row * 128 + kb));
                }
                uint32_t bfr[4][2];
                #pragma unroll
                for (int nt = 0; nt < 4; nt++) {
                    int row = warp_n * 32 + nt * 8 + (lane & 7);
                    int kb  = kk * 32 + (((lane >> 3) & 1) << 4);
                    ldsm_x2(bfr[nt], bbase + sw128(row * 128 + kb));
                }
                #pragma unroll
                for (int mt = 0; mt < 4; mt++)
                    #pragma unroll
                    for (int nt = 0; nt < 4; nt++)
                        mma16816(acc[mt][nt], afr[mt], bfr[nt]);
            }
        }
    }

    const int gid = lane >> 2;
    const int tg  = lane & 3;
    #pragma unroll
    for (int mt = 0; mt < 4; mt++) {
        int row0 = bm + warp_m * 64 + mt * 16 + gid;
        #pragma unroll
        for (int nt = 0; nt < 4; nt++) {
            int col = bn + warp_n * 32 + nt * 8 + tg * 2;
            if (col < Ntot) {
                float b0 = bias ? bias[col] : 0.0f;
                float b1 = bias ? bias[col + 1] : 0.0f;
                float2 v0 = make_float2(acc[mt][nt][0] + b0, acc[mt][nt][1] + b1);
                float2 v1 = make_float2(acc[mt][nt][2] + b0, acc[mt][nt][3] + b1);
                *(float2*)(C + (size_t)row0 * ldc + col) = v0;
                *(float2*)(C + (size_t)(row0 + 8) * ldc + col) = v1;
            }
        }
    }
}

// ============ persistent-loop device pieces ============

// grid-wide barrier (all NCTA CTAs resident). gpu-scope fence flushes L1 (CCTL.IVALL)
// so cross-SM partials are never stale.
__device__ __forceinline__ void grid_bar() {
    __syncthreads();
    if (threadIdx.x == 0) {
        __threadfence();
        unsigned gen = *((volatile unsigned*)&g_bar_gen);
        if (atomicAdd(&g_bar_count, 1) == NCTA - 1) {
            g_bar_count = 0;
            __threadfence();
            atomicExch(&g_bar_gen, gen + 1);
        } else {
            while (*((volatile unsigned*)&g_bar_gen) == gen) __nanosleep(64);
        }
        __threadfence();
    }
    __syncthreads();
}

// 128x128 MMA tile, 3-pass split-bf16, fp32 partial out.
// A rows 0..127 (lda), B rows bn..bn+127 (ldb), k from kb, nchunks x 64.
__device__ __forceinline__ void gemm_tile_128(
    char* smem, uint32_t sb,
    const __nv_bfloat16* __restrict__ Ahi, const __nv_bfloat16* __restrict__ Alo, int lda,
    const __nv_bfloat16* __restrict__ Bhi, const __nv_bfloat16* __restrict__ Blo, int ldb,
    int bn, int kb, int nchunks,
    float* __restrict__ C, int ldc)
{
    const int tid = threadIdx.x;
    const int wid = tid >> 5;
    const int lane = tid & 31;
    const int warp_m = wid & 1;
    const int warp_n = wid >> 1;

    float acc[4][4][4];
    #pragma unroll
    for (int i = 0; i < 4; i++)
        #pragma unroll
        for (int j = 0; j < 4; j++)
            #pragma unroll
            for (int r = 0; r < 4; r++) acc[i][j][r] = 0.0f;

    for (int kc = 0; kc < nchunks; kc++) {
        if (kc > 0) __syncthreads();
        #pragma unroll
        for (int t = 0; t < 2; t++) {
            const __nv_bfloat16* src = t ? Alo : Ahi;
            const uint32_t dstbase = t * 16384;
            #pragma unroll
            for (int j = 0; j < 4; j++) {
                int v = tid + j * 256;
                int row = v >> 3, c8 = v & 7;
                uint4 val = *(const uint4*)(src + (size_t)row * lda + kb + kc * 64 + c8 * 8);
                *(uint4*)(smem + dstbase + sw128(row * 128 + c8 * 16)) = val;
            }
        }
        #pragma unroll
        for (int t = 0; t < 2; t++) {
            const __nv_bfloat16* src = t ? Blo : Bhi;
            const uint32_t dstbase = 32768 + t * 16384;
            #pragma unroll
            for (int j = 0; j < 4; j++) {
                int v = tid + j * 256;
                int row = v >> 3, c8 = v & 7;
                uint4 val = *(const uint4*)(src + (size_t)(bn + row) * ldb + kb + kc * 64 + c8 * 8);
                *(uint4*)(smem + dstbase + sw128(row * 128 + c8 * 16)) = val;
            }
        }
        __syncthreads();

        #pragma unroll
        for (int pass = 0; pass < 3; pass++) {
            const uint32_t abase = sb + ((pass == 2) ? 16384 : 0);
            const uint32_t bbase = sb + 32768 + ((pass == 1) ? 16384 : 0);
            #pragma unroll
            for (int kk = 0; kk < 4; kk++) {
                uint32_t afr[4][4];
                #pragma unroll
                for (int mt = 0; mt < 4; mt++) {
                    int row = warp_m * 64 + mt * 16 + (lane & 15);
                    int kbb = kk * 32 + ((lane >> 4) << 4);
                    ldsm_x4(afr[mt], abase + sw128(row * 128 + kbb));
                }
                uint32_t bfr[4][2];
                #pragma unroll
                for (int nt = 0; nt < 4; nt++) {
                    int row = warp_n * 32 + nt * 8 + (lane & 7);
                    int kbb = kk * 32 + (((lane >> 3) & 1) << 4);
                    ldsm_x2(bfr[nt], bbase + sw128(row * 128 + kbb));
                }
                #pragma unroll
                for (int mt = 0; mt < 4; mt++)
                    #pragma unroll
                    for (int nt = 0; nt < 4; nt++)
                        mma16816(acc[mt][nt], afr[mt], bfr[nt]);
            }
        }
    }

    const int gid = lane >> 2;
    const int tg  = lane & 3;
    #pragma unroll
    for (int mt = 0; mt < 4; mt++) {
        int row0 = warp_m * 64 + mt * 16 + gid;
        #pragma unroll
        for (int nt = 0; nt < 4; nt++) {
            int col = bn + warp_n * 32 + nt * 8 + tg * 2;
            float2 v0 = make_float2(acc[mt][nt][0], acc[mt][nt][1]);
            float2 v1 = make_float2(acc[mt][nt][2], acc[mt][nt][3]);
            *(float2*)(C + (size_t)row0 * ldc + col) = v0;
            *(float2*)(C + (size_t)(row0 + 8) * ldc + col) = v1;
        }
    }
}

// ============ persistent loop kernel ============
__global__ void __launch_bounds__(256, 1)
loop_kernel(const __nv_bfloat16* __restrict__ Wn2h, const __nv_bfloat16* __restrict__ Wn2l,
            const __nv_bfloat16* __restrict__ Wd2h, const __nv_bfloat16* __restrict__ Wd2l,
            const __nv_bfloat16* __restrict__ Wch,  const __nv_bfloat16* __restrict__ Wcl,
            const float* __restrict__ attnx, const float* __restrict__ attdx,
            const float* __restrict__ b_attn, const float* __restrict__ cnn,
            const float* __restrict__ b_ih, const float* __restrict__ b_hh,
            float* __restrict__ c,
            __nv_bfloat16* __restrict__ xhh, __nv_bfloat16* __restrict__ xhl,
            __nv_bfloat16* __restrict__ ath, __nv_bfloat16* __restrict__ atl,
            __nv_bfloat16* __restrict__ hidh, __nv_bfloat16* __restrict__ hidl,
            float* __restrict__ alogp, float* __restrict__ x2p, float* __restrict__ gp)
{
    extern __shared__ char smem[];
    const uint32_t sb = smem_u32(smem);
    const int bid = blockIdx.x;
    const int tid = threadIdx.x;
    float* red = (float*)smem;

    // ---------- t = 0: gates = [feat|0] @ Wcat^T, then LSTM ----------
    {
        int ntile = bid >> 3, kz = bid & 7;
        gemm_tile_128(smem, sb, xhh, xhl, 1024, Wch, Wcl, 1024,
                      ntile * 128, kz * 128, 2, gp + (size_t)kz * BB * H4, H4);
    }
    grid_bar();
    // lstm phase t=0
    {
        #pragma unroll
        for (int i = 0; i < 2; i++) {
            int idx = bid * 512 + tid + i * 256;
            int b = idx >> 9, n = idx & 511;
            float gi = b_ih[n]        + b_hh[n];
            float gf = b_ih[512 + n]  + b_hh[512 + n];
            float gg = b_ih[1024 + n] + b_hh[1024 + n];
            float go = b_ih[1536 + n] + b_hh[1536 + n];
            #pragma unroll
            for (int p = 0; p < 8; p++) {
                const float* base = gp + (size_t)p * BB * H4 + (size_t)b * H4;
                gi += base[n]; gf += base[512 + n]; gg += base[1024 + n]; go += base[1536 + n];
            }
            gi = sigmoidf_(gi); gf = sigmoidf_(gf); gg = tanhf(gg); go = sigmoidf_(go);
            float cc = gf * c[idx] + gi * gg;
            float hh = go * tanhf(cc);
            c[idx] = cc;
            split_write(hh, xhh, xhl, (size_t)b * 1024 + 512 + n);
            split_write(hh, hidh, hidl, idx);
        }
    }
    grid_bar();

    // ---------- recurrent loop ----------
    for (int t = 1; t <= TT; t++) {
        const float* attnx_t = attnx + (size_t)t * BB * AA;
        const float* attdx_t = attdx + (size_t)t * BB * EE;

        // Phase 1: alog partials = h @ Wn2^T  (16 n-tiles x 8 kz, Kchunk=64)
        {
            int ntile = bid >> 3, kz = bid & 7;
            gemm_tile_128(smem, sb, xhh + 512, xhl + 512, 1024, Wn2h, Wn2l, HH,
                          ntile * 128, kz * 64, 1, alogp + (size_t)kz * BB * AA, AA);
        }
        grid_bar();

        // Phase 2: softmax + attend (CTA = batch row)
        {
            float v[8];
            float mx = -1e30f;
            #pragma unroll
            for (int j = 0; j < 8; j++) {
                int col = tid + j * 256;
                size_t o = (size_t)bid * AA + col;
                float s = attnx_t[o] + b_attn[col];
                #pragma unroll
                for (int p = 0; p < 8; p++) s += alogp[(size_t)p * BB * AA + o];
                v[j] = s;
                mx = fmaxf(mx, s);
            }
            red[tid] = mx;
            __syncthreads();
            for (int s = 128; s > 0; s >>= 1) {
                if (tid < s) red[tid] = fmaxf(red[tid], red[tid + s]);
                __syncthreads();
            }
            mx = red[0];
            __syncthreads();
            float sum = 0.0f;
            #pragma unroll
            for (int j = 0; j < 8; j++) { v[j] = expf(v[j] - mx); sum += v[j]; }
            red[tid] = sum;
            __syncthreads();
            for (int s = 128; s > 0; s >>= 1) {
                if (tid < s) red[tid] += red[tid + s];
                __syncthreads();
            }
            float inv = 1.0f / red[0];
            __syncthreads();
            #pragma unroll
            for (int j = 0; j < 8; j++) {
                int col = tid + j * 256;
                size_t o = (size_t)bid * AA + col;
                split_write(cnn[o] * v[j] * inv, ath, atl, o);
            }
        }
        grid_bar();

        // Phase 3: x2 partials = att @ Wd2^T  (4 n-tiles x 32 kz, Kchunk=64)
        {
            int ntile = bid >> 5, kz = bid & 31;
            gemm_tile_128(smem, sb, ath, atl, AA, Wd2h, Wd2l, AA,
                          ntile * 128, kz * 64, 1, x2p + (size_t)kz * BB * EE, EE);
        }
        grid_bar();

        // Phase 4: combine x2 -> xh[:, :512]
        {
            #pragma unroll
            for (int i = 0; i < 2; i++) {
                int idx = bid * 512 + tid + i * 256;
                int b = idx >> 9, e = idx & 511;
                float s = attdx_t[idx];
                #pragma unroll
                for (int p = 0; p < 32; p++) s += x2p[(size_t)p * BB * EE + idx];
                split_write(s, xhh, xhl, (size_t)b * 1024 + e);
            }
        }
        grid_bar();

        // Phase 5: gate partials = [x2|h] @ Wcat^T  (16 n-tiles x 8 kz, Kchunk=128)
        {
            int ntile = bid >> 3, kz = bid & 7;
            gemm_tile_128(smem, sb, xhh, xhl, 1024, Wch, Wcl, 1024,
                          ntile * 128, kz * 128, 2, gp + (size_t)kz * BB * H4, H4);
        }
        grid_bar();

        // Phase 6: LSTM pointwise
        {
            __nv_bfloat16* hh_t = hidh + (size_t)t * BB * HH;
            __nv_bfloat16* hl_t = hidl + (size_t)t * BB * HH;
            #pragma unroll
            for (int i = 0; i < 2; i++) {
                int idx = bid * 512 + tid + i * 256;
                int b = idx >> 9, n = idx & 511;
                float gi = b_ih[n]        + b_hh[n];
                float gf = b_ih[512 + n]  + b_hh[512 + n];
                float gg = b_ih[1024 + n] + b_hh[1024 + n];
                float go = b_ih[1536 + n] + b_hh[1536 + n];
                #pragma unroll
                for (int p = 0; p < 8; p++) {
                    const float* base = gp + (size_t)p * BB * H4 + (size_t)b * H4;
                    gi += base[n]; gf += base[512 + n]; gg += base[1024 + n]; go += base[1536 + n];
                }
                gi = sigmoidf_(gi); gf = sigmoidf_(gf); gg = tanhf(gg); go = sigmoidf_(go);
                float cc = gf * c[idx] + gi * gg;
                float hh = go * tanhf(cc);
                c[idx] = cc;
                split_write(hh, xhh, xhl, (size_t)b * 1024 + 512 + n);
                split_write(hh, hh_t, hl_t, idx);
            }
        }
        grid_bar();
    }
}

// ================= setup kernels =================

__global__ void build_xs_kernel(const float* __restrict__ features,
                                const int*   __restrict__ captions,
                                const float* __restrict__ table,
                                __nv_bfloat16* __restrict__ hi,
                                __nv_bfloat16* __restrict__ lo)
{
    int idx = blockIdx.x * blockDim.x + threadIdx.x;
    if (idx >= MTOT * EE) return;
    int e = idx % EE;
    int b = (idx / EE) % BB;
    int t = idx / (EE * BB);
    float v;
    if (t == 0) v = features[b * EE + e];
    else {
        int tok = captions[b * TT + (t - 1)];
        v = table[tok * EE + e];
    }
    split_write(v, hi, lo, idx);
}

// all five weight splits in one kernel
#define S1 (AA*EE)
#define S2 (AA*HH)
#define S3 (EE*EE)
#define S4 (EE*AA)
#define S5 (VV*HH)
__global__ void convert_all_kernel(const float* __restrict__ W_attn,
                                   const float* __restrict__ W_attd,
                                   const float* __restrict__ W_out,
                                   __nv_bfloat16* __restrict__ Wnh, __nv_bfloat16* __restrict__ Wnl,
                                   __nv_bfloat16* __restrict__ Wn2h, __nv_bfloat16* __restrict__ Wn2l,
                                   __nv_bfloat16* __restrict__ Wdh, __nv_bfloat16* __restrict__ Wdl,
                                   __nv_bfloat16* __restrict__ Wd2h, __nv_bfloat16* __restrict__ Wd2l,
                                   __nv_bfloat16* __restrict__ Woh, __nv_bfloat16* __restrict__ Wol)
{
    int idx = blockIdx.x * blockDim.x + threadIdx.x;
    if (idx < S1) {
        int r = idx / EE, cc = idx % EE;
        split_write(W_attn[(size_t)r * 1024 + cc], Wnh, Wnl, idx);
        return;
    }
    idx -= S1;
    if (idx < S2) {
        int r = idx / HH, cc = idx % HH;
        split_write(W_attn[(size_t)r * 1024 + EE + cc], Wn2h, Wn2l, idx);
        return;
    }
    idx -= S2;
    if (idx < S3) {
        int r = idx / EE, cc = idx % EE;
        split_write(W_attd[(size_t)r * 2560 + cc], Wdh, Wdl, idx);
        return;
    }
    idx -= S3;
    if (idx < S4) {
        int r = idx / AA, cc = idx % AA;
        split_write(W_attd[(size_t)r * 2560 + EE + cc], Wd2h, Wd2l, idx);
        return;
    }
    idx -= S4;
    if (idx < S5) {
        split_write(W_out[idx], Woh, Wol, idx);
    }
}

__global__ void pack_wcat_kernel(const float* __restrict__ Wih,
                                 const float* __restrict__ Whh,
                                 __nv_bfloat16* __restrict__ hi,
                                 __nv_bfloat16* __restrict__ lo)
{
    int idx = blockIdx.x * blockDim.x + threadIdx.x;
    if (idx >= H4 * 1024) return;
    int n = idx / 1024, k = idx % 1024;
    float v = (k < 512) ? Wih[n * 512 + k] : Whh[n * 512 + (k - 512)];
    split_write(v, hi, lo, idx);
}

__global__ void init_state_kernel(const float* __restrict__ features,
                                  __nv_bfloat16* __restrict__ xh_hi,
                                  __nv_bfloat16* __restrict__ xh_lo,
                                  float* __restrict__ c)
{
    int idx = blockIdx.x * blockDim.x + threadIdx.x;
    if (idx < BB * 1024) {
        int b = idx / 1024, k = idx % 1024;
        float v = (k < 512) ? features[b * 512 + k] : 0.0f;
        split_write(v, xh_hi, xh_lo, idx);
    }
    if (idx < BB * HH) c[idx] = 0.0f;
}

// ---------------- host ----------------

extern "C" void kernel_launch(void* const* d_in, const int* in_sizes, int n_in,
                              void* d_out, int out_size)
{
    const float* features = (const float*)d_in[0];
    const float* cnn      = (const float*)d_in[1];
    const int*   captions = (const int*)  d_in[2];
    const float* table    = (const float*)d_in[4];
    const float* W_ih     = (const float*)d_in[5];
    const float* W_hh     = (const float*)d_in[6];
    const float* b_ih     = (const float*)d_in[7];
    const float* b_hh     = (const float*)d_in[8];
    const float* W_attn   = (const float*)d_in[9];
    const float* b_attn   = (const float*)d_in[10];
    const float* W_attd   = (const float*)d_in[11];
    const float* b_attd   = (const float*)d_in[12];
    const float* W_out    = (const float*)d_in[13];
    const float* b_out    = (const float*)d_in[14];
    float* out = (float*)d_out;

    float *p_c, *p_attnx, *p_attdx, *p_alogp, *p_x2p, *p_gp;
    __nv_bfloat16 *p_xsh, *p_xsl, *p_hih, *p_hil, *p_xhh, *p_xhl, *p_ath, *p_atl,
                  *p_Woh, *p_Wol, *p_Wnh, *p_Wnl, *p_Wn2h, *p_Wn2l,
                  *p_Wdh, *p_Wdl, *p_Wd2h, *p_Wd2l, *p_Wch, *p_Wcl;
    cudaGetSymbolAddress((void**)&p_c,     g_c);
    cudaGetSymbolAddress((void**)&p_attnx, g_attnx);
    cudaGetSymbolAddress((void**)&p_attdx, g_attdx);
    cudaGetSymbolAddress((void**)&p_alogp, g_alogp);
    cudaGetSymbolAddress((void**)&p_x2p,   g_x2p);
    cudaGetSymbolAddress((void**)&p_gp,    g_gp);
    cudaGetSymbolAddress((void**)&p_xsh,   g_xs_hi);
    cudaGetSymbolAddress((void**)&p_xsl,   g_xs_lo);
    cudaGetSymbolAddress((void**)&p_hih,   g_hid_hi);
    cudaGetSymbolAddress((void**)&p_hil,   g_hid_lo);
    cudaGetSymbolAddress((void**)&p_xhh,   g_xh_hi);
    cudaGetSymbolAddress((void**)&p_xhl,   g_xh_lo);
    cudaGetSymbolAddress((void**)&p_ath,   g_att_hi);
    cudaGetSymbolAddress((void**)&p_atl,   g_att_lo);
    cudaGetSymbolAddress((void**)&p_Woh,   g_Woh);
    cudaGetSymbolAddress((void**)&p_Wol,   g_Wol);
    cudaGetSymbolAddress((void**)&p_Wnh,   g_Wnh);
    cudaGetSymbolAddress((void**)&p_Wnl,   g_Wnl);
    cudaGetSymbolAddress((void**)&p_Wn2h,  g_Wn2h);
    cudaGetSymbolAddress((void**)&p_Wn2l,  g_Wn2l);
    cudaGetSymbolAddress((void**)&p_Wdh,   g_Wdh);
    cudaGetSymbolAddress((void**)&p_Wdl,   g_Wdl);
    cudaGetSymbolAddress((void**)&p_Wd2h,  g_Wd2h);
    cudaGetSymbolAddress((void**)&p_Wd2l,  g_Wd2l);
    cudaGetSymbolAddress((void**)&p_Wch,   g_Wch);
    cudaGetSymbolAddress((void**)&p_Wcl,   g_Wcl);

    cudaFuncSetAttribute(gemm_mma_kernel, cudaFuncAttributeMaxDynamicSharedMemorySize, 65536);
    cudaFuncSetAttribute(loop_kernel,     cudaFuncAttributeMaxDynamicSharedMemorySize, 65536);

    // ---- setup ----
    build_xs_kernel<<<(MTOT*EE + 255)/256, 256>>>(features, captions, table, p_xsh, p_xsl);
    pack_wcat_kernel<<<(H4*1024 + 255)/256, 256>>>(W_ih, W_hh, p_Wch, p_Wcl);
    init_state_kernel<<<(BB*1024 + 255)/256, 256>>>(features, p_xhh, p_xhl, p_c);
    {
        int total = S1 + S2 + S3 + S4 + S5;
        convert_all_kernel<<<(total + 255)/256, 256>>>(
            W_attn, W_attd, W_out,
            p_Wnh, p_Wnl, p_Wn2h, p_Wn2l, p_Wdh, p_Wdl, p_Wd2h, p_Wd2l, p_Woh, p_Wol);
    }

    // ---- precompute x-dependent attention terms (batched) ----
    gemm_mma_kernel<<<dim3(AA/128, MTOT/128), 256, 65536>>>(
        p_xsh, p_xsl, p_Wnh, p_Wnl, nullptr, p_attnx, AA, AA, EE);
    gemm_mma_kernel<<<dim3(EE/128, MTOT/128), 256, 65536>>>(
        p_xsh, p_xsl, p_Wdh, p_Wdl, b_attd, p_attdx, EE, EE, EE);

    // ---- persistent recurrent loop (t=0 init + 31 steps in ONE launch) ----
    loop_kernel<<<NCTA, 256, 65536>>>(
        p_Wn2h, p_Wn2l, p_Wd2h, p_Wd2l, p_Wch, p_Wcl,
        p_attnx, p_attdx, b_attn, cnn, b_ih, b_hh, p_c,
        p_xhh, p_xhl, p_ath, p_atl, p_hih, p_hil,
        p_alogp, p_x2p, p_gp);

    // ---- output projection: logits = hidden @ W_out^T + b_out ----
    gemm_mma_kernel<<<dim3((VV + 127)/128, MTOT/128), 256, 65536>>>(
        p_hih, p_hil, p_Woh, p_Wol, b_out, out, VV, VV, HH);
}

// round 10
// speedup vs baseline: 1.1058x; 1.1058x over previous
#include <cuda_runtime.h>
#include <cuda_bf16.h>
#include <cstdint>
#include <math.h>

// Problem dims
#define BB  128
#define TT  31
#define TP1 32
#define EE  512
#define HH  512
#define H4  2048
#define VV  10000
#define AA  2048
#define MTOT 4096   // (T+1)*B rows

// ---------------- device scratch (static, no allocs) ----------------
__device__ float g_c    [BB*HH];
__device__ float g_attnx[MTOT*AA];
__device__ float g_attdx[MTOT*EE];
__device__ float g_alogp[4*BB*AA];     // attn-logit split-K partials (z=4)
__device__ float g_x2p  [16*BB*EE];    // x2 partials (z=16)
__device__ float g_gp   [8*BB*H4];     // gate partials (z=8)

// bf16 split activation buffers
__device__ __nv_bfloat16 g_xs_hi [MTOT*EE], g_xs_lo [MTOT*EE];
__device__ __nv_bfloat16 g_hid_hi[MTOT*HH], g_hid_lo[MTOT*HH];
__device__ __nv_bfloat16 g_xh_hi [BB*1024], g_xh_lo [BB*1024];   // [x2|h]
__device__ __nv_bfloat16 g_att_hi[BB*AA],   g_att_lo[BB*AA];

// bf16 split weights
__device__ __nv_bfloat16 g_Woh[VV*HH],   g_Wol[VV*HH];     // W_out
__device__ __nv_bfloat16 g_Wnh[AA*EE],   g_Wnl[AA*EE];     // W_attn x-part
__device__ __nv_bfloat16 g_Wn2h[AA*HH],  g_Wn2l[AA*HH];    // W_attn h-part
__device__ __nv_bfloat16 g_Wdh[EE*EE],   g_Wdl[EE*EE];     // W_attd x-part
__device__ __nv_bfloat16 g_Wd2h[EE*AA],  g_Wd2l[EE*AA];    // W_attd a-part
__device__ __nv_bfloat16 g_Wch[H4*1024], g_Wcl[H4*1024];   // [W_ih|W_hh]

// ================= warp-MMA helpers (sm_80+ baseline PTX only) =================
__device__ __forceinline__ uint32_t smem_u32(const void* p) {
    uint32_t a;
    asm("{ .reg .u64 t; cvta.to.shared.u64 t, %1; cvt.u32.u64 %0, t; }" : "=r"(a) : "l"(p));
    return a;
}
__device__ __forceinline__ uint32_t sw128(uint32_t b) { return b ^ ((b >> 3) & 0x70); }

__device__ __forceinline__ void ldsm_x4(uint32_t* r, uint32_t addr) {
    asm volatile("ldmatrix.sync.aligned.m8n8.x4.shared.b16 {%0,%1,%2,%3}, [%4];"
                 : "=r"(r[0]), "=r"(r[1]), "=r"(r[2]), "=r"(r[3]) : "r"(addr));
}
__device__ __forceinline__ void ldsm_x2(uint32_t* r, uint32_t addr) {
    asm volatile("ldmatrix.sync.aligned.m8n8.x2.shared.b16 {%0,%1}, [%2];"
                 : "=r"(r[0]), "=r"(r[1]) : "r"(addr));
}
__device__ __forceinline__ void mma16816(float* d, const uint32_t* a, const uint32_t* b) {
    asm volatile("mma.sync.aligned.m16n8k16.row.col.f32.bf16.bf16.f32 "
                 "{%0,%1,%2,%3}, {%4,%5,%6,%7}, {%8,%9}, {%0,%1,%2,%3};"
                 : "+f"(d[0]), "+f"(d[1]), "+f"(d[2]), "+f"(d[3])
                 : "r"(a[0]), "r"(a[1]), "r"(a[2]), "r"(a[3]), "r"(b[0]), "r"(b[1]));
}
__device__ __forceinline__ void cpasync16(uint32_t dst, const void* src, int sz) {
    asm volatile("cp.async.cg.shared.global [%0], [%1], 16, %2;"
                 :: "r"(dst), "l"(src), "r"(sz));
}
#define CP_COMMIT() asm volatile("cp.async.commit_group;" ::: "memory")
#define CP_WAIT1()  asm volatile("cp.async.wait_group 1;" ::: "memory")
#define CP_WAIT0()  asm volatile("cp.async.wait_group 0;" ::: "memory")

__device__ __forceinline__ void split_write(float x, __nv_bfloat16* hi, __nv_bfloat16* lo, size_t i) {
    __nv_bfloat16 h = __float2bfloat16(x);
    hi[i] = h;
    lo[i] = __float2bfloat16(x - __bfloat162float(h));
}
__device__ __forceinline__ float sigmoidf_(float x) {
    return 1.0f / (1.0f + expf(-x));
}

// ============ big warp-MMA split-bf16 GEMM, cp.async double-buffered ============
// A: [M x K] hi/lo, M mult of 128; B: [Ntot x K] hi/lo (row-guarded); K mult of 64.
// SMEM: 2 buffers x 64KB: {Ahi 16K, Alo 16K, Bhi 16K, Blo 16K}
__global__ void __launch_bounds__(256, 1)
gemm_mma_kernel(const __nv_bfloat16* __restrict__ Ahi,
                const __nv_bfloat16* __restrict__ Alo,
                const __nv_bfloat16* __restrict__ Bhi,
                const __nv_bfloat16* __restrict__ Blo,
                const float* __restrict__ bias,
                float* __restrict__ C, int ldc, int Ntot, int K)
{
    extern __shared__ char smem[];
    const uint32_t sb = smem_u32(smem);
    const int tid = threadIdx.x;
    const int wid = tid >> 5;
    const int lane = tid & 31;
    const int warp_m = wid & 1;
    const int warp_n = wid >> 1;
    const int bm = blockIdx.y * 128;
    const int bn = blockIdx.x * 128;

    float acc[4][4][4];
    #pragma unroll
    for (int i = 0; i < 4; i++)
        #pragma unroll
        for (int j = 0; j < 4; j++)
            #pragma unroll
            for (int r = 0; r < 4; r++) acc[i][j][r] = 0.0f;

    const __nv_bfloat16* srcs[4] = {Ahi, Alo, Bhi, Blo};
    const int nchunks = K >> 6;

    // issue one chunk's loads into buffer `buf`
    auto issue = [&](int kc, int buf) {
        const uint32_t bufbase = sb + buf * 65536;
        #pragma unroll
        for (int t = 0; t < 4; t++) {
            const __nv_bfloat16* src = srcs[t];
            const uint32_t dstbase = bufbase + t * 16384;
            #pragma unroll
            for (int j = 0; j < 4; j++) {
                int v = tid + j * 256;
                int row = v >> 3, c8 = v & 7;
                int sz = 16;
                const __nv_bfloat16* sp;
                if (t < 2) {
                    sp = src + (size_t)(bm + row) * K + kc * 64 + c8 * 8;
                } else {
                    int gn = bn + row;
                    if (gn >= Ntot) { gn = 0; sz = 0; }
                    sp = src + (size_t)gn * K + kc * 64 + c8 * 8;
                }
                cpasync16(dstbase + sw128(row * 128 + c8 * 16), sp, sz);
            }
        }
    };

    issue(0, 0);
    CP_COMMIT();

    for (int kc = 0; kc < nchunks; kc++) {
        const int buf = kc & 1;
        if (kc + 1 < nchunks) {
            issue(kc + 1, buf ^ 1);
            CP_COMMIT();
            CP_WAIT1();
        } else {
            CP_WAIT0();
        }
        __syncthreads();

        const uint32_t bufbase = sb + buf * 65536;
        #pragma unroll
        for (int pass = 0; pass < 3; pass++) {
            const uint32_t abase = bufbase + ((pass == 2) ? 16384 : 0);
            const uint32_t bbase = bufbase + 32768 + ((pass == 1) ? 16384 : 0);
            #pragma unroll
            for (int kk = 0; kk < 4; kk++) {
                uint32_t afr[4][4];
                #pragma unroll
                for (int mt = 0; mt < 4; mt++) {
                    int row = warp_m * 64 + mt * 16 + (lane & 15);
                    int kb  = kk * 32 + ((lane >> 4) << 4);
                    ldsm_x4(afr[mt], abase + sw128(row * 128 + kb));
                }
                uint32_t bfr[4][2];
                #pragma unroll
                for (int nt = 0; nt < 4; nt++) {
                    int row = warp_n * 32 + nt * 8 + (lane & 7);
                    int kb  = kk * 32 + (((lane >> 3) & 1) << 4);
                    ldsm_x2(bfr[nt], bbase + sw128(row * 128 + kb));
                }
                #pragma unroll
                for (int mt = 0; mt < 4; mt++)
                    #pragma unroll
                    for (int nt = 0; nt < 4; nt++)
                        mma16816(acc[mt][nt], afr[mt], bfr[nt]);
            }
        }
        __syncthreads();
    }

    const int gid = lane >> 2;
    const int tg  = lane & 3;
    #pragma unroll
    for (int mt = 0; mt < 4; mt++) {
        int row0 = bm + warp_m * 64 + mt * 16 + gid;
        #pragma unroll
        for (int nt = 0; nt < 4; nt++) {
            int col = bn + warp_n * 32 + nt * 8 + tg * 2;
            if (col < Ntot) {
                float b0 = bias ? bias[col] : 0.0f;
                float b1 = bias ? bias[col + 1] : 0.0f;
                float2 v0 = make_float2(acc[mt][nt][0] + b0, acc[mt][nt][1] + b1);
                float2 v1 = make_float2(acc[mt][nt][2] + b0, acc[mt][nt][3] + b1);
                *(float2*)(C + (size_t)row0 * ldc + col) = v0;
                *(float2*)(C + (size_t)(row0 + 8) * ldc + col) = v1;
            }
        }
    }
}

// ============ step warp-MMA GEMM: M=128, split-K, fp32 partials ============
__global__ void __launch_bounds__(256, 1)
gemm_mma_step(const __nv_bfloat16* __restrict__ Ahi,
              const __nv_bfloat16* __restrict__ Alo, int lda,
              const __nv_bfloat16* __restrict__ Bhi,
              const __nv_bfloat16* __restrict__ Blo, int ldb,
              float* __restrict__ Cpart, int N, size_t pstride, int Kchunk)
{
    extern __shared__ char smem[];
    const uint32_t sb = smem_u32(smem);
    const int tid = threadIdx.x;
    const int wid = tid >> 5;
    const int lane = tid & 31;
    const int warp_m = wid & 1;
    const int warp_n = wid >> 1;
    const int bn = blockIdx.x * 128;
    const int kb = blockIdx.z * Kchunk;
    float* C = Cpart + (size_t)blockIdx.z * pstride;

    float acc[4][4][4];
    #pragma unroll
    for (int i = 0; i < 4; i++)
        #pragma unroll
        for (int j = 0; j < 4; j++)
            #pragma unroll
            for (int r = 0; r < 4; r++) acc[i][j][r] = 0.0f;

    const int nchunks = Kchunk >> 6;
    for (int kc = 0; kc < nchunks; kc++) {
        if (kc > 0) __syncthreads();
        #pragma unroll
        for (int t = 0; t < 2; t++) {
            const __nv_bfloat16* src = t ? Alo : Ahi;
            const uint32_t dstbase = t * 16384;
            #pragma unroll
            for (int j = 0; j < 4; j++) {
                int v = tid + j * 256;
                int row = v >> 3, c8 = v & 7;
                uint4 val = *(const uint4*)(src + (size_t)row * lda + kb + kc * 64 + c8 * 8);
                *(uint4*)(smem + dstbase + sw128(row * 128 + c8 * 16)) = val;
            }
        }
        #pragma unroll
        for (int t = 0; t < 2; t++) {
            const __nv_bfloat16* src = t ? Blo : Bhi;
            const uint32_t dstbase = 32768 + t * 16384;
            #pragma unroll
            for (int j = 0; j < 4; j++) {
                int v = tid + j * 256;
                int row = v >> 3, c8 = v & 7;
                uint4 val = *(const uint4*)(src + (size_t)(bn + row) * ldb + kb + kc * 64 + c8 * 8);
                *(uint4*)(smem + dstbase + sw128(row * 128 + c8 * 16)) = val;
            }
        }
        __syncthreads();

        #pragma unroll
        for (int pass = 0; pass < 3; pass++) {
            const uint32_t abase = sb + ((pass == 2) ? 16384 : 0);
            const uint32_t bbase = sb + 32768 + ((pass == 1) ? 16384 : 0);
            #pragma unroll
            for (int kk = 0; kk < 4; kk++) {
                uint32_t afr[4][4];
                #pragma unroll
                for (int mt = 0; mt < 4; mt++) {
                    int row = warp_m * 64 + mt * 16 + (lane & 15);
                    int kbb = kk * 32 + ((lane >> 4) << 4);
                    ldsm_x4(afr[mt], abase + sw128(row * 128 + kbb));
                }
                uint32_t bfr[4][2];
                #pragma unroll
                for (int nt = 0; nt < 4; nt++) {
                    int row = warp_n * 32 + nt * 8 + (lane & 7);
                    int kbb = kk * 32 + (((lane >> 3) & 1) << 4);
                    ldsm_x2(bfr[nt], bbase + sw128(row * 128 + kbb));
                }
                #pragma unroll
                for (int mt = 0; mt < 4; mt++)
                    #pragma unroll
                    for (int nt = 0; nt < 4; nt++)
                        mma16816(acc[mt][nt], afr[mt], bfr[nt]);
            }
        }
    }

    const int gid = lane >> 2;
    const int tg  = lane & 3;
    #pragma unroll
    for (int mt = 0; mt < 4; mt++) {
        int row0 = warp_m * 64 + mt * 16 + gid;
        #pragma unroll
        for (int nt = 0; nt < 4; nt++) {
            int col = bn + warp_n * 32 + nt * 8 + tg * 2;
            float2 v0 = make_float2(acc[mt][nt][0], acc[mt][nt][1]);
            float2 v1 = make_float2(acc[mt][nt][2], acc[mt][nt][3]);
            *(float2*)(C + (size_t)row0 * N + col) = v0;
            *(float2*)(C + (size_t)(row0 + 8) * N + col) = v1;
        }
    }
}

// ================= setup / pointwise kernels =================

__global__ void build_xs_kernel(const float* __restrict__ features,
                                const int*   __restrict__ captions,
                                const float* __restrict__ table,
                                __nv_bfloat16* __restrict__ hi,
                                __nv_bfloat16* __restrict__ lo)
{
    int idx = blockIdx.x * blockDim.x + threadIdx.x;
    if (idx >= MTOT * EE) return;
    int e = idx % EE;
    int b = (idx / EE) % BB;
    int t = idx / (EE * BB);
    float v;
    if (t == 0) v = features[b * EE + e];
    else {
        int tok = captions[b * TT + (t - 1)];
        v = table[tok * EE + e];
    }
    split_write(v, hi, lo, idx);
}

// all five weight splits in one kernel
#define S1 (AA*EE)
#define S2 (AA*HH)
#define S3 (EE*EE)
#define S4 (EE*AA)
#define S5 (VV*HH)
__global__ void convert_all_kernel(const float* __restrict__ W_attn,
                                   const float* __restrict__ W_attd,
                                   const float* __restrict__ W_out,
                                   __nv_bfloat16* __restrict__ Wnh, __nv_bfloat16* __restrict__ Wnl,
                                   __nv_bfloat16* __restrict__ Wn2h, __nv_bfloat16* __restrict__ Wn2l,
                                   __nv_bfloat16* __restrict__ Wdh, __nv_bfloat16* __restrict__ Wdl,
                                   __nv_bfloat16* __restrict__ Wd2h, __nv_bfloat16* __restrict__ Wd2l,
                                   __nv_bfloat16* __restrict__ Woh, __nv_bfloat16* __restrict__ Wol)
{
    int idx = blockIdx.x * blockDim.x + threadIdx.x;
    if (idx < S1) {
        int r = idx / EE, cc = idx % EE;
        split_write(W_attn[(size_t)r * 1024 + cc], Wnh, Wnl, idx);
        return;
    }
    idx -= S1;
    if (idx < S2) {
        int r = idx / HH, cc = idx % HH;
        split_write(W_attn[(size_t)r * 1024 + EE + cc], Wn2h, Wn2l, idx);
        return;
    }
    idx -= S2;
    if (idx < S3) {
        int r = idx / EE, cc = idx % EE;
        split_write(W_attd[(size_t)r * 2560 + cc], Wdh, Wdl, idx);
        return;
    }
    idx -= S3;
    if (idx < S4) {
        int r = idx / AA, cc = idx % AA;
        split_write(W_attd[(size_t)r * 2560 + EE + cc], Wd2h, Wd2l, idx);
        return;
    }
    idx -= S4;
    if (idx < S5) {
        split_write(W_out[idx], Woh, Wol, idx);
    }
}

__global__ void pack_wcat_kernel(const float* __restrict__ Wih,
                                 const float* __restrict__ Whh,
                                 __nv_bfloat16* __restrict__ hi,
                                 __nv_bfloat16* __restrict__ lo)
{
    int idx = blockIdx.x * blockDim.x + threadIdx.x;
    if (idx >= H4 * 1024) return;
    int n = idx / 1024, k = idx % 1024;
    float v = (k < 512) ? Wih[n * 512 + k] : Whh[n * 512 + (k - 512)];
    split_write(v, hi, lo, idx);
}

__global__ void init_state_kernel(const float* __restrict__ features,
                                  __nv_bfloat16* __restrict__ xh_hi,
                                  __nv_bfloat16* __restrict__ xh_lo,
                                  float* __restrict__ c)
{
    int idx = blockIdx.x * blockDim.x + threadIdx.x;
    if (idx < BB * 1024) {
        int b = idx / 1024, k = idx % 1024;
        float v = (k < 512) ? features[b * 512 + k] : 0.0f;
        split_write(v, xh_hi, xh_lo, idx);
    }
    if (idx < BB * HH) c[idx] = 0.0f;
}

// softmax over 2048 (4 partials + attnx + bias), attend, write bf16 hi/lo
__global__ void softmax_attend_kernel(const float* __restrict__ parts,
                                      const float* __restrict__ attnx,
                                      const float* __restrict__ b_attn,
                                      const float* __restrict__ cnn,
                                      __nv_bfloat16* __restrict__ att_hi,
                                      __nv_bfloat16* __restrict__ att_lo)
{
    const int b = blockIdx.x;
    const int tid = threadIdx.x;     // 256
    __shared__ float red[256];

    float v[8];
    float mx = -1e30f;
    #pragma unroll
    for (int j = 0; j < 8; j++) {
        int col = tid + j * 256;
        size_t o = (size_t)b * AA + col;
        float s = attnx[o] + b_attn[col];
        #pragma unroll
        for (int p = 0; p < 4; p++) s += parts[(size_t)p * BB * AA + o];
        v[j] = s;
        mx = fmaxf(mx, s);
    }
    red[tid] = mx;
    __syncthreads();
    for (int s = 128; s > 0; s >>= 1) {
        if (tid < s) red[tid] = fmaxf(red[tid], red[tid + s]);
        __syncthreads();
    }
    mx = red[0];
    __syncthreads();

    float sum = 0.0f;
    #pragma unroll
    for (int j = 0; j < 8; j++) { v[j] = expf(v[j] - mx); sum += v[j]; }
    red[tid] = sum;
    __syncthreads();
    for (int s = 128; s > 0; s >>= 1) {
        if (tid < s) red[tid] += red[tid + s];
        __syncthreads();
    }
    float inv = 1.0f / red[0];

    #pragma unroll
    for (int j = 0; j < 8; j++) {
        int col = tid + j * 256;
        size_t o = (size_t)b * AA + col;
        split_write(cnn[o] * v[j] * inv, att_hi, att_lo, o);
    }
}

// x2 = sum of 16 partials + attdx  -> xh[:, :512] bf16 hi/lo
__global__ void combine_x2_kernel(const float* __restrict__ parts,
                                  const float* __restrict__ attdx,
                                  __nv_bfloat16* __restrict__ xh_hi,
                                  __nv_bfloat16* __restrict__ xh_lo)
{
    int idx = blockIdx.x * blockDim.x + threadIdx.x;
    if (idx >= BB * EE) return;
    int b = idx / EE, e = idx % EE;
    float s = attdx[idx];
    #pragma unroll
    for (int p = 0; p < 16; p++) s += parts[(size_t)p * BB * EE + idx];
    split_write(s, xh_hi, xh_lo, (size_t)b * 1024 + e);
}

// LSTM pointwise: combine 8 gate partials + biases; update c; write h
__global__ void lstm_pointwise_kernel(const float* __restrict__ gp,
                                      const float* __restrict__ b_ih,
                                      const float* __restrict__ b_hh,
                                      __nv_bfloat16* __restrict__ xh_hi,
                                      __nv_bfloat16* __restrict__ xh_lo,
                                      float* __restrict__ c,
                                      __nv_bfloat16* __restrict__ hid_hi,
                                      __nv_bfloat16* __restrict__ hid_lo)
{
    int idx = blockIdx.x * blockDim.x + threadIdx.x;
    if (idx >= BB * HH) return;
    int b = idx / HH, n = idx % HH;
    float gi = b_ih[n]        + b_hh[n];
    float gf = b_ih[512 + n]  + b_hh[512 + n];
    float gg = b_ih[1024 + n] + b_hh[1024 + n];
    float go = b_ih[1536 + n] + b_hh[1536 + n];
    #pragma unroll
    for (int p = 0; p < 8; p++) {
        const float* base = gp + (size_t)p * BB * H4 + (size_t)b * H4;
        gi += base[n];
        gf += base[512 + n];
        gg += base[1024 + n];
        go += base[1536 + n];
    }
    gi = sigmoidf_(gi);
    gf = sigmoidf_(gf);
    gg = tanhf(gg);
    go = sigmoidf_(go);
    float cc = gf * c[idx] + gi * gg;
    float hh = go * tanhf(cc);
    c[idx] = cc;
    split_write(hh, xh_hi, xh_lo, (size_t)b * 1024 + 512 + n);
    split_write(hh, hid_hi, hid_lo, idx);
}

// ---------------- host ----------------

extern "C" void kernel_launch(void* const* d_in, const int* in_sizes, int n_in,
                              void* d_out, int out_size)
{
    const float* features = (const float*)d_in[0];
    const float* cnn      = (const float*)d_in[1];
    const int*   captions = (const int*)  d_in[2];
    const float* table    = (const float*)d_in[4];
    const float* W_ih     = (const float*)d_in[5];
    const float* W_hh     = (const float*)d_in[6];
    const float* b_ih     = (const float*)d_in[7];
    const float* b_hh     = (const float*)d_in[8];
    const float* W_attn   = (const float*)d_in[9];
    const float* b_attn   = (const float*)d_in[10];
    const float* W_attd   = (const float*)d_in[11];
    const float* b_attd   = (const float*)d_in[12];
    const float* W_out    = (const float*)d_in[13];
    const float* b_out    = (const float*)d_in[14];
    float* out = (float*)d_out;

    float *p_c, *p_attnx, *p_attdx, *p_alogp, *p_x2p, *p_gp;
    __nv_bfloat16 *p_xsh, *p_xsl, *p_hih, *p_hil, *p_xhh, *p_xhl, *p_ath, *p_atl,
                  *p_Woh, *p_Wol, *p_Wnh, *p_Wnl, *p_Wn2h, *p_Wn2l,
                  *p_Wdh, *p_Wdl, *p_Wd2h, *p_Wd2l, *p_Wch, *p_Wcl;
    cudaGetSymbolAddress((void**)&p_c,     g_c);
    cudaGetSymbolAddress((void**)&p_attnx, g_attnx);
    cudaGetSymbolAddress((void**)&p_attdx, g_attdx);
    cudaGetSymbolAddress((void**)&p_alogp, g_alogp);
    cudaGetSymbolAddress((void**)&p_x2p,   g_x2p);
    cudaGetSymbolAddress((void**)&p_gp,    g_gp);
    cudaGetSymbolAddress((void**)&p_xsh,   g_xs_hi);
    cudaGetSymbolAddress((void**)&p_xsl,   g_xs_lo);
    cudaGetSymbolAddress((void**)&p_hih,   g_hid_hi);
    cudaGetSymbolAddress((void**)&p_hil,   g_hid_lo);
    cudaGetSymbolAddress((void**)&p_xhh,   g_xh_hi);
    cudaGetSymbolAddress((void**)&p_xhl,   g_xh_lo);
    cudaGetSymbolAddress((void**)&p_ath,   g_att_hi);
    cudaGetSymbolAddress((void**)&p_atl,   g_att_lo);
    cudaGetSymbolAddress((void**)&p_Woh,   g_Woh);
    cudaGetSymbolAddress((void**)&p_Wol,   g_Wol);
    cudaGetSymbolAddress((void**)&p_Wnh,   g_Wnh);
    cudaGetSymbolAddress((void**)&p_Wnl,   g_Wnl);
    cudaGetSymbolAddress((void**)&p_Wn2h,  g_Wn2h);
    cudaGetSymbolAddress((void**)&p_Wn2l,  g_Wn2l);
    cudaGetSymbolAddress((void**)&p_Wdh,   g_Wdh);
    cudaGetSymbolAddress((void**)&p_Wdl,   g_Wdl);
    cudaGetSymbolAddress((void**)&p_Wd2h,  g_Wd2h);
    cudaGetSymbolAddress((void**)&p_Wd2l,  g_Wd2l);
    cudaGetSymbolAddress((void**)&p_Wch,   g_Wch);
    cudaGetSymbolAddress((void**)&p_Wcl,   g_Wcl);

    cudaFuncSetAttribute(gemm_mma_kernel, cudaFuncAttributeMaxDynamicSharedMemorySize, 131072);
    cudaFuncSetAttribute(gemm_mma_step,   cudaFuncAttributeMaxDynamicSharedMemorySize, 65536);

    // ---- setup ----
    build_xs_kernel<<<(MTOT*EE + 255)/256, 256>>>(features, captions, table, p_xsh, p_xsl);
    pack_wcat_kernel<<<(H4*1024 + 255)/256, 256>>>(W_ih, W_hh, p_Wch, p_Wcl);
    init_state_kernel<<<(BB*1024 + 255)/256, 256>>>(features, p_xhh, p_xhl, p_c);
    {
        int total = S1 + S2 + S3 + S4 + S5;
        convert_all_kernel<<<(total + 255)/256, 256>>>(
            W_attn, W_attd, W_out,
            p_Wnh, p_Wnl, p_Wn2h, p_Wn2l, p_Wdh, p_Wdl, p_Wd2h, p_Wd2l, p_Woh, p_Wol);
    }

    // ---- precompute x-dependent attention terms (batched) ----
    gemm_mma_kernel<<<dim3(AA/128, MTOT/128), 256, 131072>>>(
        p_xsh, p_xsl, p_Wnh, p_Wnl, nullptr, p_attnx, AA, AA, EE);
    gemm_mma_kernel<<<dim3(EE/128, MTOT/128), 256, 131072>>>(
        p_xsh, p_xsl, p_Wdh, p_Wdl, b_attd, p_attdx, EE, EE, EE);

    // ---- t = 0: gates = [features|0] @ Wcat^T (split-K8), LSTM ----
    gemm_mma_step<<<dim3(H4/128, 1, 8), 256, 65536>>>(
        p_xhh, p_xhl, 1024, p_Wch, p_Wcl, 1024, p_gp, H4, (size_t)BB*H4, 128);
    lstm_pointwise_kernel<<<(BB*HH + 255)/256, 256>>>(
        p_gp, b_ih, b_hh, p_xhh, p_xhl, p_c, p_hih, p_hil);

    // ---- recurrent loop ----
    for (int t = 1; t <= TT; t++) {
        const float* attnx_t = p_attnx + (size_t)t * BB * AA;
        const float* attdx_t = p_attdx + (size_t)t * BB * EE;

        // attn logits partials: h @ W_attn_h^T  (split-K4, K=512)
        gemm_mma_step<<<dim3(AA/128, 1, 4), 256, 65536>>>(
            p_xhh + 512, p_xhl + 512, 1024, p_Wn2h, p_Wn2l, HH,
            p_alogp, AA, (size_t)BB*AA, 128);
        // softmax + attend -> att bf16
        softmax_attend_kernel<<<BB, 256>>>(p_alogp, attnx_t, b_attn, cnn, p_ath, p_atl);
        // x2 partials: att @ W_attd_a^T  (split-K16, K=2048)
        gemm_mma_step<<<dim3(EE/128, 1, 16), 256, 65536>>>(
            p_ath, p_atl, AA, p_Wd2h, p_Wd2l, AA,
            p_x2p, EE, (size_t)BB*EE, 128);
        // combine -> xh[:, :512] bf16
        combine_x2_kernel<<<(BB*EE + 255)/256, 256>>>(p_x2p, attdx_t, p_xhh, p_xhl);
        // gates partials: [x2|h] @ Wcat^T  (split-K8, K=1024)
        gemm_mma_step<<<dim3(H4/128, 1, 8), 256, 65536>>>(
            p_xhh, p_xhl, 1024, p_Wch, p_Wcl, 1024, p_gp, H4, (size_t)BB*H4, 128);
        // LSTM pointwise
        lstm_pointwise_kernel<<<(BB*HH + 255)/256, 256>>>(
            p_gp, b_ih, b_hh, p_xhh, p_xhl, p_c,
            p_hih + (size_t)t * BB * HH, p_hil + (size_t)t * BB * HH);
    }

    // ---- output projection: logits = hidden @ W_out^T + b_out ----
    gemm_mma_kernel<<<dim3((VV + 127)/128, MTOT/128), 256, 131072>>>(
        p_hih, p_hil, p_Woh, p_Wol, b_out, out, VV, VV, HH);
}